// round 2
// baseline (speedup 1.0000x reference)
#include <cuda_runtime.h>
#include <float.h>

#define NPTS 2048
#define BATCH 8
#define MTOT (BATCH * NPTS)

// ---------------- scratch (device globals; no runtime allocation) ------------
__device__ float g_G[(size_t)BATCH * NPTS * NPTS];   // 128 MB Gram/dist scratch
__device__ float g_xcat[(size_t)MTOT * 512];         // x1|x2|x3|x4 concatenated
__device__ float g_YZ[(size_t)MTOT * 512];           // [Y | Z] per edge layer
__device__ float g_xlocal[(size_t)MTOT * 512];
__device__ float g_xemb[(size_t)MTOT * 1024];
__device__ float g_h1[(size_t)MTOT * 256];
__device__ float g_h2[(size_t)MTOT * 256];
__device__ float g_xx[MTOT];
__device__ int   g_idx[MTOT * 20];
__device__ float g_glob[BATCH * 1024];
__device__ float g_gbias[BATCH * 256];
__device__ float g_Wc[512 * 128];                    // [W1 ; W2-W1]

// ---------------- generic tiled GEMM: out[m,o] = sum_c X[m,c]*W[o,c] ---------
// MODE 0: raw   MODE 1: lrelu(s*v+t)   MODE 2: lrelu(s*(v+gadd[b,o])+t)
// MODE 3: v + t[o]
template <int MODE>
__global__ void __launch_bounds__(256) gemm_nt(
    const float* __restrict__ Xb, int ldx, long bsX,
    const float* __restrict__ Wb, int ldw, long bsW,
    float* __restrict__ Ob, int ldo, long bsO,
    int M, int C, int O,
    const float* __restrict__ s, const float* __restrict__ t,
    const float* __restrict__ gadd)
{
    __shared__ float Xs[16][68];
    __shared__ float Ws[16][68];
    const float* X = Xb + (long)blockIdx.z * bsX;
    const float* W = Wb + (long)blockIdx.z * bsW;
    float* Out = Ob + (long)blockIdx.z * bsO;
    int m0 = blockIdx.y * 64, o0 = blockIdx.x * 64;
    int tid = threadIdx.x;
    int tx = tid & 15, ty = tid >> 4;
    int cc = tid & 15, r0 = tid >> 4;

    float acc[4][4];
#pragma unroll
    for (int i = 0; i < 4; i++)
#pragma unroll
        for (int j = 0; j < 4; j++) acc[i][j] = 0.f;

    for (int k0 = 0; k0 < C; k0 += 16) {
        int c = k0 + cc;
        bool cok = (c < C);
#pragma unroll
        for (int i = 0; i < 4; i++) {
            int m = m0 + r0 + i * 16;
            Xs[cc][r0 + i * 16] = (cok && m < M) ? X[(long)m * ldx + c] : 0.f;
            int o = o0 + r0 + i * 16;
            Ws[cc][r0 + i * 16] = (cok && o < O) ? W[(long)o * ldw + c] : 0.f;
        }
        __syncthreads();
#pragma unroll
        for (int kk = 0; kk < 16; kk++) {
            float xf[4], wf[4];
#pragma unroll
            for (int i = 0; i < 4; i++) xf[i] = Xs[kk][ty * 4 + i];
#pragma unroll
            for (int j = 0; j < 4; j++) wf[j] = Ws[kk][tx * 4 + j];
#pragma unroll
            for (int i = 0; i < 4; i++)
#pragma unroll
                for (int j = 0; j < 4; j++) acc[i][j] += xf[i] * wf[j];
        }
        __syncthreads();
    }

#pragma unroll
    for (int i = 0; i < 4; i++) {
        int m = m0 + ty * 4 + i;
        if (m >= M) continue;
#pragma unroll
        for (int j = 0; j < 4; j++) {
            int o = o0 + tx * 4 + j;
            if (o >= O) continue;
            float v = acc[i][j];
            if (MODE == 1) { v = s[o] * v + t[o]; v = v >= 0.f ? v : 0.2f * v; }
            else if (MODE == 2) {
                v = s[o] * (v + gadd[(m >> 11) * O + o]) + t[o];
                v = v >= 0.f ? v : 0.2f * v;
            }
            else if (MODE == 3) { v = v + t[o]; }
            Out[(long)m * ldo + o] = v;
        }
    }
}

// ---------------- squared row norms ------------------------------------------
__global__ void rownorm_kernel(const float* __restrict__ X, int ldx, int C,
                               float* __restrict__ xx)
{
    int m = blockIdx.x * blockDim.x + threadIdx.x;
    if (m >= MTOT) return;
    const float* p = X + (long)m * ldx;
    float a = 0.f;
    for (int c = 0; c < C; c++) a += p[c] * p[c];
    xx[m] = a;
}

// ---------------- top-20 smallest of d_j = xx_i + xx_j - 2*G[i,j] ------------
// Iterative argmin with lowest-index tiebreak (matches stable lax.top_k).
__global__ void __launch_bounds__(256) topk_kernel(
    const float* __restrict__ G, const float* __restrict__ xx,
    int* __restrict__ idxout)
{
    __shared__ float d[NPTS];
    __shared__ float wv[8];
    __shared__ int wi[8];
    int row = blockIdx.x;
    int b = row >> 11;
    const float* g = G + (long)row * NPTS;
    const float* xxb = xx + (b << 11);
    float xi = xx[row];
    int tid = threadIdx.x;

    for (int j = tid; j < NPTS; j += 256) d[j] = xi + xxb[j] - 2.f * g[j];
    __syncthreads();

    for (int it = 0; it < 20; it++) {
        float best = FLT_MAX;
        int bi = 1 << 30;
        for (int j = tid; j < NPTS; j += 256) {
            float v = d[j];
            if (v < best) { best = v; bi = j; }   // within-thread: first (lowest j) wins ties
        }
#pragma unroll
        for (int off = 16; off > 0; off >>= 1) {
            float ov = __shfl_down_sync(0xFFFFFFFFu, best, off);
            int oi = __shfl_down_sync(0xFFFFFFFFu, bi, off);
            if (ov < best || (ov == best && oi < bi)) { best = ov; bi = oi; }
        }
        if ((tid & 31) == 0) { wv[tid >> 5] = best; wi[tid >> 5] = bi; }
        __syncthreads();
        if (tid == 0) {
            best = wv[0]; bi = wi[0];
#pragma unroll
            for (int w = 1; w < 8; w++)
                if (wv[w] < best || (wv[w] == best && wi[w] < bi)) { best = wv[w]; bi = wi[w]; }
            idxout[row * 20 + it] = bi;
            d[bi] = FLT_MAX;
        }
        __syncthreads();
    }
}

// ---------------- build combined weight [W1 ; W2-W1] -------------------------
__global__ void prep_wc_kernel(const float* __restrict__ w, float* __restrict__ wc,
                               int O, int C)
{
    int i = blockIdx.x * blockDim.x + threadIdx.x;
    if (i >= O * C) return;
    int o = i / C, c = i - o * C;
    float w1 = w[(long)o * 2 * C + c];
    float w2 = w[(long)o * 2 * C + C + c];
    wc[(long)o * C + c] = w1;
    wc[(long)(O + o) * C + c] = w2 - w1;
}

// ---------------- gather-max over k neighbors + epilogue ---------------------
// out[bn,o] = lrelu(s_o * (max_k Y[b,idx[k],o] + Z[bn,o]) + t_o)
__global__ void __launch_bounds__(128) edge_max_kernel(
    const float* __restrict__ YZ, int ldyz,
    const int* __restrict__ idx,
    const float* __restrict__ s,
    const float* __restrict__ t,
    float* __restrict__ out, int ldo, int O)
{
    __shared__ int nb[20];
    int bn = blockIdx.x;
    int bbase = (bn >> 11) << 11;
    if (threadIdx.x < 20) nb[threadIdx.x] = idx[bn * 20 + threadIdx.x];
    __syncthreads();
    for (int o = threadIdx.x; o < O; o += 128) {
        float z = YZ[(long)bn * ldyz + O + o];
        float m = -FLT_MAX;
#pragma unroll
        for (int kk = 0; kk < 20; kk++) {
            float y = YZ[(long)(bbase + nb[kk]) * ldyz + o];
            m = fmaxf(m, y);
        }
        float v = s[o] * (m + z) + t[o];
        out[(long)bn * ldo + o] = v >= 0.f ? v : 0.2f * v;
    }
}

// ---------------- global max over N ------------------------------------------
__global__ void maxreduce_kernel(const float* __restrict__ xemb,
                                 float* __restrict__ glob)
{
    int o = blockIdx.x * blockDim.x + threadIdx.x;   // 0..1023
    int b = blockIdx.y;
    const float* p = xemb + (long)b * NPTS * 1024 + o;
    float m = -FLT_MAX;
    for (int n = 0; n < NPTS; n++) m = fmaxf(m, p[(long)n * 1024]);
    glob[b * 1024 + o] = m;
}

// ---------------- per-batch global-feature bias for h1 -----------------------
__global__ void gbias_kernel(const float* __restrict__ h1w,
                             const float* __restrict__ glob,
                             float* __restrict__ gb)
{
    __shared__ float gsh[1024];
    int b = blockIdx.x, o = threadIdx.x;
    for (int c = threadIdx.x; c < 1024; c += 256) gsh[c] = glob[b * 1024 + c];
    __syncthreads();
    const float* wr = h1w + (long)o * 1536 + 512;
    float acc = 0.f;
    for (int c = 0; c < 1024; c++) acc += gsh[c] * wr[c];
    gb[b * 256 + o] = acc;
}

// ---------------- host orchestration -----------------------------------------
static inline dim3 ggrid(int M, int O, int Z) {
    return dim3((O + 63) / 64, (M + 63) / 64, Z);
}

static void run_edge_layer(const float* X, int ldx, int C, int O,
                           const float* w, const float* s, const float* t,
                           float* pG, float* pxx, int* pidx, float* pWc,
                           float* pYZ, float* outcol)
{
    // 1. squared norms
    rownorm_kernel<<<(MTOT + 255) / 256, 256>>>(X, ldx, C, pxx);
    // 2. Gram matrix per batch: G[b] = X[b] X[b]^T
    gemm_nt<0><<<ggrid(NPTS, NPTS, BATCH), 256>>>(
        X, ldx, (long)NPTS * ldx, X, ldx, (long)NPTS * ldx,
        pG, NPTS, (long)NPTS * NPTS, NPTS, C, NPTS,
        nullptr, nullptr, nullptr);
    // 3. top-20 neighbors
    topk_kernel<<<MTOT, 256>>>(pG, pxx, pidx);
    // 4. combined weight [W1; W2-W1]
    prep_wc_kernel<<<(O * C + 255) / 256, 256>>>(w, pWc, O, C);
    // 5. YZ = X @ Wc^T  (raw, activation after max)
    gemm_nt<0><<<ggrid(MTOT, 2 * O, 1), 256>>>(
        X, ldx, 0L, pWc, C, 0L, pYZ, 2 * O, 0L,
        MTOT, C, 2 * O, nullptr, nullptr, nullptr);
    // 6. gather-max + lrelu epilogue, write directly into xcat column slice
    edge_max_kernel<<<MTOT, 128>>>(pYZ, 2 * O, pidx, s, t, outcol, 512, O);
}

extern "C" void kernel_launch(void* const* d_in, const int* in_sizes, int n_in,
                              void* d_out, int out_size)
{
    const float* xyz    = (const float*)d_in[0];
    const float* ec1_w  = (const float*)d_in[1];
    const float* ec1_s  = (const float*)d_in[2];
    const float* ec1_t  = (const float*)d_in[3];
    const float* ec2_w  = (const float*)d_in[4];
    const float* ec2_s  = (const float*)d_in[5];
    const float* ec2_t  = (const float*)d_in[6];
    const float* ec3_w  = (const float*)d_in[7];
    const float* ec3_s  = (const float*)d_in[8];
    const float* ec3_t  = (const float*)d_in[9];
    const float* ec4_w  = (const float*)d_in[10];
    const float* ec4_s  = (const float*)d_in[11];
    const float* ec4_t  = (const float*)d_in[12];
    const float* fuse_w = (const float*)d_in[13];
    const float* fuse_s = (const float*)d_in[14];
    const float* fuse_t = (const float*)d_in[15];
    const float* emb_w  = (const float*)d_in[16];
    const float* emb_s  = (const float*)d_in[17];
    const float* emb_t  = (const float*)d_in[18];
    const float* h1_w   = (const float*)d_in[19];
    const float* h1_s   = (const float*)d_in[20];
    const float* h1_t   = (const float*)d_in[21];
    const float* h2_w   = (const float*)d_in[22];
    const float* h2_s   = (const float*)d_in[23];
    const float* h2_t   = (const float*)d_in[24];
    const float* h3_w   = (const float*)d_in[25];
    const float* h3_b   = (const float*)d_in[26];
    float* out = (float*)d_out;

    float *pG, *pxcat, *pYZ, *pxloc, *pxemb, *ph1, *ph2, *pxx, *pWc, *pglob, *pgb;
    int* pidx;
    cudaGetSymbolAddress((void**)&pG, g_G);
    cudaGetSymbolAddress((void**)&pxcat, g_xcat);
    cudaGetSymbolAddress((void**)&pYZ, g_YZ);
    cudaGetSymbolAddress((void**)&pxloc, g_xlocal);
    cudaGetSymbolAddress((void**)&pxemb, g_xemb);
    cudaGetSymbolAddress((void**)&ph1, g_h1);
    cudaGetSymbolAddress((void**)&ph2, g_h2);
    cudaGetSymbolAddress((void**)&pxx, g_xx);
    cudaGetSymbolAddress((void**)&pWc, g_Wc);
    cudaGetSymbolAddress((void**)&pglob, g_glob);
    cudaGetSymbolAddress((void**)&pgb, g_gbias);
    cudaGetSymbolAddress((void**)&pidx, g_idx);

    // EdgeConv stack; each layer writes its output into a column slice of xcat
    run_edge_layer(xyz,         3,   3,   64,  ec1_w, ec1_s, ec1_t, pG, pxx, pidx, pWc, pYZ, pxcat + 0);
    run_edge_layer(pxcat + 0,   512, 64,  64,  ec2_w, ec2_s, ec2_t, pG, pxx, pidx, pWc, pYZ, pxcat + 64);
    run_edge_layer(pxcat + 64,  512, 64,  128, ec3_w, ec3_s, ec3_t, pG, pxx, pidx, pWc, pYZ, pxcat + 128);
    run_edge_layer(pxcat + 128, 512, 128, 256, ec4_w, ec4_s, ec4_t, pG, pxx, pidx, pWc, pYZ, pxcat + 256);

    // fuse: (16384,512) -> 512, lrelu
    gemm_nt<1><<<ggrid(MTOT, 512, 1), 256>>>(
        pxcat, 512, 0L, fuse_w, 512, 0L, pxloc, 512, 0L,
        MTOT, 512, 512, fuse_s, fuse_t, nullptr);
    // emb: 512 -> 1024, lrelu
    gemm_nt<1><<<ggrid(MTOT, 1024, 1), 256>>>(
        pxloc, 512, 0L, emb_w, 512, 0L, pxemb, 1024, 0L,
        MTOT, 512, 1024, emb_s, emb_t, nullptr);
    // global max over N
    maxreduce_kernel<<<dim3(4, BATCH), 256>>>(pxemb, pglob);
    // per-batch bias from global feature through h1_w[:,512:]
    gbias_kernel<<<BATCH, 256>>>(h1_w, pglob, pgb);
    // h1: 512 -> 256 with per-batch gadd, lrelu (ldw = 1536, first 512 cols)
    gemm_nt<2><<<ggrid(MTOT, 256, 1), 256>>>(
        pxloc, 512, 0L, h1_w, 1536, 0L, ph1, 256, 0L,
        MTOT, 512, 256, h1_s, h1_t, pgb);
    // h2: 256 -> 256, lrelu
    gemm_nt<1><<<ggrid(MTOT, 256, 1), 256>>>(
        ph1, 256, 0L, h2_w, 256, 0L, ph2, 256, 0L,
        MTOT, 256, 256, h2_s, h2_t, nullptr);
    // h3: 256 -> 13, +bias, no activation -> d_out
    gemm_nt<3><<<ggrid(MTOT, 13, 1), 256>>>(
        ph2, 256, 0L, h3_w, 256, 0L, out, 13, 0L,
        MTOT, 256, 13, nullptr, h3_b, nullptr);
}